// round 5
// baseline (speedup 1.0000x reference)
#include <cuda_runtime.h>
#include <cuda_bf16.h>
#include <math.h>
#include <stdint.h>

#define BB 8
#define SS 1024
#define EE 512
#define HH 8
#define DD 64

// ---------------- scratch (__device__ globals; no allocation) ---------------
__device__ __nv_bfloat16 g_xh[3L*8192*512];    // q,k,v bf16 hi (proj inputs)
__device__ __nv_bfloat16 g_xl[3L*8192*512];    // q,k,v bf16 lo
__device__ __nv_bfloat16 g_wh[3L*512*512];     // Wk,Wv,Wo hi
__device__ __nv_bfloat16 g_wl[3L*512*512];     // Wk,Wv,Wo lo
__device__ __nv_bfloat16 g_qbh[BB*HH*SS*DD];   // projected heads, bf16 hi/lo
__device__ __nv_bfloat16 g_qbl[BB*HH*SS*DD];
__device__ __nv_bfloat16 g_kbh[BB*HH*SS*DD];
__device__ __nv_bfloat16 g_kbl[BB*HH*SS*DD];
__device__ __nv_bfloat16 g_vbh[BB*HH*SS*DD];
__device__ __nv_bfloat16 g_vbl[BB*HH*SS*DD];
__device__ __nv_bfloat16 g_aoh[8192L*512];     // attention out hi
__device__ __nv_bfloat16 g_aol[8192L*512];     // attention out lo

// ---------------- helpers ---------------------------------------------------
__device__ __forceinline__ uint32_t smem_u32(const void* p) {
    uint32_t a;
    asm("{ .reg .u64 t; cvta.to.shared.u64 t, %1; cvt.u32.u64 %0, t; }"
        : "=r"(a) : "l"(p));
    return a;
}
__device__ __forceinline__ void ldsm_x4(uint32_t r[4], uint32_t addr) {
    asm volatile("ldmatrix.sync.aligned.m8n8.x4.shared.b16 {%0,%1,%2,%3}, [%4];"
        : "=r"(r[0]), "=r"(r[1]), "=r"(r[2]), "=r"(r[3]) : "r"(addr));
}
__device__ __forceinline__ void ldsm_x2(uint32_t r[2], uint32_t addr) {
    asm volatile("ldmatrix.sync.aligned.m8n8.x2.shared.b16 {%0,%1}, [%2];"
        : "=r"(r[0]), "=r"(r[1]) : "r"(addr));
}
__device__ __forceinline__ void mma_bf16(float c[4], const uint32_t a[4],
                                         const uint32_t b[2]) {
    asm volatile(
        "mma.sync.aligned.m16n8k16.row.col.f32.bf16.bf16.f32 "
        "{%0,%1,%2,%3}, {%4,%5,%6,%7}, {%8,%9}, {%0,%1,%2,%3};"
        : "+f"(c[0]), "+f"(c[1]), "+f"(c[2]), "+f"(c[3])
        : "r"(a[0]), "r"(a[1]), "r"(a[2]), "r"(a[3]), "r"(b[0]), "r"(b[1]));
}
__device__ __forceinline__ float warpMax(float v) {
    #pragma unroll
    for (int o = 16; o > 0; o >>= 1) v = fmaxf(v, __shfl_xor_sync(0xffffffffu, v, o));
    return v;
}
__device__ __forceinline__ float warpSum(float v) {
    #pragma unroll
    for (int o = 16; o > 0; o >>= 1) v += __shfl_xor_sync(0xffffffffu, v, o);
    return v;
}

// ============================================================================
// Split kernel: fp32 -> bf16 (hi, lo) for q/k/v and Wk/Wv/Wo.
// ============================================================================
__global__ __launch_bounds__(256)
void split_kernel(const float* __restrict__ q, const float* __restrict__ k,
                  const float* __restrict__ v,
                  const float* __restrict__ Wk, const float* __restrict__ Wv,
                  const float* __restrict__ Wo)
{
    const long NX4 = 3L * 8192 * 512 / 4;
    const long NW4 = 3L * 512 * 512 / 4;
    long i4 = (long)blockIdx.x * blockDim.x + threadIdx.x;
    if (i4 >= NX4 + NW4) return;

    const float* src;
    __nv_bfloat16 *dh, *dl;
    long off4;
    if (i4 < NX4) {
        long z = i4 >> 20;
        off4 = i4 & ((1L << 20) - 1);
        src = (z == 0) ? q : ((z == 1) ? k : v);
        dh = g_xh + z * (8192L * 512);
        dl = g_xl + z * (8192L * 512);
    } else {
        long j4 = i4 - NX4;
        long w = j4 / 65536;
        off4 = j4 - w * 65536;
        src = (w == 0) ? Wk : ((w == 1) ? Wv : Wo);
        dh = g_wh + w * (512L * 512);
        dl = g_wl + w * (512L * 512);
    }
    float4 x = *(const float4*)(src + off4 * 4);
    __nv_bfloat16 h0 = __float2bfloat16(x.x), h1 = __float2bfloat16(x.y);
    __nv_bfloat16 h2 = __float2bfloat16(x.z), h3 = __float2bfloat16(x.w);
    __nv_bfloat162 hp0(h0, h1), hp1(h2, h3);
    __nv_bfloat162 lp0(__float2bfloat16(x.x - __bfloat162float(h0)),
                       __float2bfloat16(x.y - __bfloat162float(h1)));
    __nv_bfloat162 lp1(__float2bfloat16(x.z - __bfloat162float(h2)),
                       __float2bfloat16(x.w - __bfloat162float(h3)));
    *(__nv_bfloat162*)(dh + off4 * 4)     = hp0;
    *(__nv_bfloat162*)(dh + off4 * 4 + 2) = hp1;
    *(__nv_bfloat162*)(dl + off4 * 4)     = lp0;
    *(__nv_bfloat162*)(dl + off4 * 4 + 2) = lp1;
}

// ============================================================================
// Tensor-core GEMM (3x bf16 split): C[128,128] = A @ B^T + bias
//   mode 0 (z): A=split(q/k/v), B=split(Wk/Wk/Wv); C -> bf16 hi/lo head layout
//   mode 1:     A=split(ao),    B=split(Wo);       C -> fp32 out
// ============================================================================
#define TPAD 144
#define TSZ  18432     // 128*144
#define GEMM_SMEM (4*TSZ)

__global__ __launch_bounds__(256, 1)
void gemm_bf16(const float* __restrict__ bk, const float* __restrict__ bv,
               const float* __restrict__ bo, float* __restrict__ out, int mode)
{
    extern __shared__ char sm[];
    const uint32_t sb = smem_u32(sm);
    const int tid = threadIdx.x;
    const int wid = tid >> 5;
    const int lane = tid & 31;

    const __nv_bfloat16 *Ah, *Al, *Bh, *Bl;
    const float* bias;
    __nv_bfloat16 *Ybh = 0, *Ybl = 0;
    if (mode == 0) {
        int z = blockIdx.z;
        Ah = g_xh + z * (8192L * 512);
        Al = g_xl + z * (8192L * 512);
        long w = (z == 2) ? 1 : 0;
        Bh = g_wh + w * (512L * 512);
        Bl = g_wl + w * (512L * 512);
        bias = (z == 2) ? bv : bk;
        Ybh = (z == 0) ? g_qbh : ((z == 1) ? g_kbh : g_vbh);
        Ybl = (z == 0) ? g_qbl : ((z == 1) ? g_kbl : g_vbl);
    } else {
        Ah = g_aoh; Al = g_aol;
        Bh = g_wh + 2 * (512L * 512);
        Bl = g_wl + 2 * (512L * 512);
        bias = bo;
    }

    const int m0 = blockIdx.x * 128;
    const int n0 = blockIdx.y * 128;
    const int wm = (wid >> 2) * 64;
    const int wn = (wid & 3) * 32;

    const uint32_t sA_h = sb;
    const uint32_t sA_l = sb + TSZ;
    const uint32_t sB_h = sb + 2*TSZ;
    const uint32_t sB_l = sb + 3*TSZ;

    float c[4][4][4];
    #pragma unroll
    for (int a = 0; a < 4; a++)
        #pragma unroll
        for (int b = 0; b < 4; b++)
            #pragma unroll
            for (int d = 0; d < 4; d++) c[a][b][d] = 0.f;

    for (int ch = 0; ch < 8; ch++) {
        __syncthreads();
        #pragma unroll
        for (int i = 0; i < 16; i++) {
            int slot = tid + i * 256;
            int arr  = slot >> 10;
            int r    = (slot >> 3) & 127;
            int cg   = slot & 7;
            const __nv_bfloat16* src =
                (arr == 0) ? Ah : ((arr == 1) ? Al : ((arr == 2) ? Bh : Bl));
            int grow = ((arr < 2) ? m0 : n0) + r;
            uint4 vdat = *(const uint4*)(src + (long)grow * 512 + ch * 64 + cg * 8);
            *(uint4*)(sm + arr * TSZ + r * TPAD + cg * 16) = vdat;
        }
        __syncthreads();

        #pragma unroll
        for (int ks = 0; ks < 4; ks++) {
            uint32_t bh[4][2], bl[4][2];
            #pragma unroll
            for (int ni = 0; ni < 4; ni++) {
                uint32_t addr = (uint32_t)((wn + ni*8 + (lane & 7)) * TPAD
                               + (ks*16 + ((lane >> 3) & 1) * 8) * 2);
                ldsm_x2(bh[ni], sB_h + addr);
                ldsm_x2(bl[ni], sB_l + addr);
            }
            #pragma unroll
            for (int mi = 0; mi < 4; mi++) {
                uint32_t addr = (uint32_t)((wm + mi*16 + (lane & 15)) * TPAD
                               + (ks*16 + (lane >> 4) * 8) * 2);
                uint32_t ah[4], al[4];
                ldsm_x4(ah, sA_h + addr);
                ldsm_x4(al, sA_l + addr);
                #pragma unroll
                for (int ni = 0; ni < 4; ni++) {
                    mma_bf16(c[mi][ni], ah, bh[ni]);
                    mma_bf16(c[mi][ni], ah, bl[ni]);
                    mma_bf16(c[mi][ni], al, bh[ni]);
                }
            }
        }
    }

    const int qrow = lane >> 2;
    const int qcol = (lane & 3) * 2;
    #pragma unroll
    for (int mi = 0; mi < 4; mi++) {
        #pragma unroll
        for (int ni = 0; ni < 4; ni++) {
            #pragma unroll
            for (int half = 0; half < 2; half++) {
                int m  = m0 + wm + mi*16 + qrow + half*8;
                int cn = n0 + wn + ni*8 + qcol;
                float x0 = c[mi][ni][half*2 + 0] + bias[cn];
                float x1 = c[mi][ni][half*2 + 1] + bias[cn + 1];
                if (mode == 0) {
                    int b = m >> 10, s = m & 1023;
                    int h = cn >> 6, d = cn & 63;
                    long idx = (((long)(b*HH + h)) * SS + s) * DD + d;
                    __nv_bfloat16 h0 = __float2bfloat16(x0);
                    __nv_bfloat16 h1 = __float2bfloat16(x1);
                    *(__nv_bfloat162*)&Ybh[idx] = __nv_bfloat162(h0, h1);
                    *(__nv_bfloat162*)&Ybl[idx] = __nv_bfloat162(
                        __float2bfloat16(x0 - __bfloat162float(h0)),
                        __float2bfloat16(x1 - __bfloat162float(h1)));
                } else {
                    *(float2*)&out[(long)m * 512 + cn] = make_float2(x0, x1);
                }
            }
        }
    }
}

// ============================================================================
// Attention kernel: per CTA = (b, h, 32-query block). Tensor-core phases A/C.
// SMEM (bytes):
//   sc  fp32 [32][1028]                 131584
//   kh/kl bf16 tile [64][72] (144B/row)   9216 each  (K tile, later V^T tile)
//   qh/ql bf16 tile [32][72]              4608 each  (Q tile, later P tile)
// total 159232
// ============================================================================
#define SCS 1028
#define AOFF_KH 131584
#define AOFF_KL (131584 + 9216)
#define AOFF_QH (131584 + 2*9216)
#define AOFF_QL (131584 + 2*9216 + 4608)
#define ATTN_SMEM (131584 + 2*9216 + 2*4608)

__global__ __launch_bounds__(256, 1)
void attn_kernel(const float* __restrict__ gammas)
{
    extern __shared__ char asm_[];
    float* sc = (float*)asm_;
    const uint32_t sb = smem_u32(asm_);
    const uint32_t s_kh = sb + AOFF_KH;
    const uint32_t s_kl = sb + AOFF_KL;
    const uint32_t s_qh = sb + AOFF_QH;
    const uint32_t s_ql = sb + AOFF_QL;

    const int i0  = blockIdx.x * 32;
    const int h   = blockIdx.y;
    const int b   = blockIdx.z;
    const int tid = threadIdx.x;
    const int w    = tid >> 5;
    const int lane = tid & 31;

    const long base = ((long)(b*HH + h)) * SS * DD;
    const __nv_bfloat16* Qh = g_qbh + base;
    const __nv_bfloat16* Ql = g_qbl + base;
    const __nv_bfloat16* Kh = g_kbh + base;
    const __nv_bfloat16* Kl = g_kbl + base;
    const __nv_bfloat16* Vh = g_vbh + base;
    const __nv_bfloat16* Vl = g_vbl + base;

    const float g = gammas[h];
    const float gamma = -log1pf(expf(g));

    // ---- load Q tile (32x64 bf16 hi/lo): 512 uint4 slots ----
    #pragma unroll
    for (int i = 0; i < 2; i++) {
        int slot = tid + i * 256;
        int arr = slot >> 8;               // 0:hi 1:lo
        int r   = (slot >> 3) & 31;
        int cg  = slot & 7;
        const __nv_bfloat16* src = arr ? Ql : Qh;
        uint4 v4 = *(const uint4*)(src + (long)(i0 + r) * DD + cg * 8);
        *(uint4*)(asm_ + (arr ? AOFF_QL : AOFF_QH) + r * 144 + cg * 16) = v4;
    }

    const int ntiles = (i0 + 31) / 64 + 1;
    const int tend   = ntiles * 64;
    const int wn = w * 8;                  // warp's 8-col slice

    // -------- Phase A: scores = Q K^T / 8  (mma, 3x split) --------
    for (int t = 0; t < ntiles; t++) {
        __syncthreads();
        #pragma unroll
        for (int i = 0; i < 4; i++) {       // K tile 64x64 hi/lo = 1024 slots
            int slot = tid + i * 256;
            int arr = slot >> 9;
            int r   = (slot >> 3) & 63;
            int cg  = slot & 7;
            const __nv_bfloat16* src = arr ? Kl : Kh;
            uint4 v4 = *(const uint4*)(src + (long)(t*64 + r) * DD + cg * 8);
            *(uint4*)(asm_ + (arr ? AOFF_KL : AOFF_KH) + r * 144 + cg * 16) = v4;
        }
        __syncthreads();

        float c[2][4] = {};
        #pragma unroll
        for (int ks = 0; ks < 4; ks++) {
            uint32_t bh[2], bl[2];
            uint32_t baddr = (uint32_t)((wn + (lane & 7)) * 144
                            + (ks*16 + ((lane >> 3) & 1) * 8) * 2);
            ldsm_x2(bh, s_kh + baddr);
            ldsm_x2(bl, s_kl + baddr);
            #pragma unroll
            for (int mt = 0; mt < 2; mt++) {
                uint32_t aaddr = (uint32_t)((mt*16 + (lane & 15)) * 144
                                + (ks*16 + (lane >> 4) * 8) * 2);
                uint32_t ah[4], al[4];
                ldsm_x4(ah, s_qh + aaddr);
                ldsm_x4(al, s_ql + aaddr);
                mma_bf16(c[mt], ah, bh);
                mma_bf16(c[mt], ah, bl);
                mma_bf16(c[mt], al, bh);
            }
        }
        #pragma unroll
        for (int mt = 0; mt < 2; mt++) {
            int row = mt*16 + (lane >> 2);
            int col = t*64 + wn + (lane & 3) * 2;
            sc[row*SCS + col]       = c[mt][0] * 0.125f;
            sc[row*SCS + col + 1]   = c[mt][1] * 0.125f;
            sc[(row+8)*SCS + col]   = c[mt][2] * 0.125f;
            sc[(row+8)*SCS + col+1] = c[mt][3] * 0.125f;
        }
    }
    __syncthreads();

    // -------- Phase B: softmax -> suffix-scan decay -> softmax --------------
    for (int r = 0; r < 4; r++) {
        const int i = i0 + w*4 + r;
        float* row = sc + (w*4 + r) * SCS;

        if (i == 0) {
            for (int j = lane; j < tend; j += 32) row[j] = 0.f;
            continue;
        }

        float mx = -3.4e38f;
        for (int j = lane; j <= i; j += 32) mx = fmaxf(mx, row[j]);
        mx = warpMax(mx);
        float sum = 0.f;
        for (int j = lane; j <= i; j += 32) sum += __expf(row[j] - mx);
        sum = warpSum(sum);
        const float inv = 1.f / sum;

        float carry = 0.f;
        const int nch = (i >> 5) + 1;
        for (int ccc = 0; ccc < nch; ccc++) {
            int j = ccc*32 + lane;
            float sorig = (j <= i) ? row[j] : 0.f;
            float e = (j <= i) ? __expf(sorig - mx) * inv : 0.f;
            float incl = e;
            #pragma unroll
            for (int o = 1; o < 32; o <<= 1) {
                float t2 = __shfl_up_sync(0xffffffffu, incl, o);
                if (lane >= o) incl += t2;
            }
            float pref = carry + incl;
            carry = __shfl_sync(0xffffffffu, pref, 31);
            float suffix = 1.f - pref;
            float pos = (float)(i - j);
            float dist = sqrtf(fmaxf(suffix * pos, 0.f));
            float eff = __expf(dist * gamma);
            eff = fminf(fmaxf(eff, 1e-5f), 1e5f);
            if (j <= i) row[j] = sorig * eff;
        }

        float m2 = -3.4e38f;
        for (int j = lane; j <= i; j += 32) m2 = fmaxf(m2, row[j]);
        m2 = warpMax(m2);
        float s2 = 0.f;
        for (int j = lane; j <= i; j += 32) s2 += __expf(row[j] - m2);
        s2 = warpSum(s2);
        const float inv2 = 1.f / s2;
        for (int j = lane; j < tend; j += 32)
            row[j] = (j <= i) ? __expf(row[j] - m2) * inv2 : 0.f;
    }

    // -------- Phase C: out = P @ V  (mma, 3x split; V^T staged) --------
    float o[2][4] = {};

    for (int t = 0; t < ntiles; t++) {
        __syncthreads();
        // stage V^T tile: vt[d][j] from V[j][d], hi/lo (transposed scalar writes)
        #pragma unroll
        for (int i = 0; i < 2; i++) {
            int slot = tid + i * 256;          // 512 slots: 64 j-rows x 8 groups
            int j  = slot >> 3;
            int d0 = (slot & 7) * 8;
            union { uint4 u; __nv_bfloat16 e[8]; } th, tl;
            th.u = *(const uint4*)(Vh + (long)(t*64 + j) * DD + d0);
            tl.u = *(const uint4*)(Vl + (long)(t*64 + j) * DD + d0);
            #pragma unroll
            for (int u = 0; u < 8; u++) {
                *(__nv_bfloat16*)(asm_ + AOFF_KH + (d0+u)*144 + j*2) = th.e[u];
                *(__nv_bfloat16*)(asm_ + AOFF_KL + (d0+u)*144 + j*2) = tl.e[u];
            }
        }
        // stage P tile bf16 hi/lo: rows 32 x 64 cols, 8 elems/thread
        {
            int row = tid >> 3;
            int c0  = (tid & 7) * 8;
            #pragma unroll
            for (int u = 0; u < 8; u++) {
                float x = sc[row*SCS + t*64 + c0 + u];
                __nv_bfloat16 hh = __float2bfloat16(x);
                *(__nv_bfloat16*)(asm_ + AOFF_QH + row*144 + (c0+u)*2) = hh;
                *(__nv_bfloat16*)(asm_ + AOFF_QL + row*144 + (c0+u)*2) =
                    __float2bfloat16(x - __bfloat162float(hh));
            }
        }
        __syncthreads();

        #pragma unroll
        for (int ks = 0; ks < 4; ks++) {
            uint32_t bh[2], bl[2];
            uint32_t baddr = (uint32_t)((wn + (lane & 7)) * 144
                            + (ks*16 + ((lane >> 3) & 1) * 8) * 2);
            ldsm_x2(bh, s_kh + baddr);
            ldsm_x2(bl, s_kl + baddr);
            #pragma unroll
            for (int mt = 0; mt < 2; mt++) {
                uint32_t aaddr = (uint32_t)((mt*16 + (lane & 15)) * 144
                                + (ks*16 + (lane >> 4) * 8) * 2);
                uint32_t ah[4], al[4];
                ldsm_x4(ah, s_qh + aaddr);
                ldsm_x4(al, s_ql + aaddr);
                mma_bf16(o[mt], ah, bh);
                mma_bf16(o[mt], ah, bl);
                mma_bf16(o[mt], al, bh);
            }
        }
    }

    // epilogue: o regs -> g_aoh/g_aol (bf16 hi/lo), layout [B*S][E]
    #pragma unroll
    for (int mt = 0; mt < 2; mt++) {
        #pragma unroll
        for (int half = 0; half < 2; half++) {
            int s = i0 + mt*16 + (lane >> 2) + half*8;
            int e = h*DD + wn + (lane & 3) * 2;
            long idx = ((long)(b*SS + s)) * EE + e;
            float x0 = o[mt][half*2 + 0];
            float x1 = o[mt][half*2 + 1];
            __nv_bfloat16 h0 = __float2bfloat16(x0);
            __nv_bfloat16 h1 = __float2bfloat16(x1);
            *(__nv_bfloat162*)&g_aoh[idx] = __nv_bfloat162(h0, h1);
            *(__nv_bfloat162*)&g_aol[idx] = __nv_bfloat162(
                __float2bfloat16(x0 - __bfloat162float(h0)),
                __float2bfloat16(x1 - __bfloat162float(h1)));
        }
    }
}

// ============================================================================
extern "C" void kernel_launch(void* const* d_in, const int* in_sizes, int n_in,
                              void* d_out, int out_size)
{
    const float* q      = (const float*)d_in[0];
    const float* k      = (const float*)d_in[1];
    const float* v      = (const float*)d_in[2];
    const float* Wk     = (const float*)d_in[3];
    const float* bk     = (const float*)d_in[4];
    const float* Wv     = (const float*)d_in[5];
    const float* bv     = (const float*)d_in[6];
    const float* Wo     = (const float*)d_in[7];
    const float* bo     = (const float*)d_in[8];
    const float* gammas = (const float*)d_in[9];
    float* out = (float*)d_out;

    cudaFuncSetAttribute(attn_kernel, cudaFuncAttributeMaxDynamicSharedMemorySize,
                         ATTN_SMEM);
    cudaFuncSetAttribute(gemm_bf16, cudaFuncAttributeMaxDynamicSharedMemorySize,
                         GEMM_SMEM);

    const long total4 = 3L*8192*512/4 + 3L*512*512/4;
    split_kernel<<<(int)((total4 + 255) / 256), 256>>>(q, k, v, Wk, Wv, Wo);
    gemm_bf16<<<dim3(64, 4, 3), 256, GEMM_SMEM>>>(bk, bv, bo, out, 0);
    attn_kernel<<<dim3(SS/32, HH, BB), 256, ATTN_SMEM>>>(gammas);
    gemm_bf16<<<dim3(64, 4, 1), 256, GEMM_SMEM>>>(bk, bv, bo, out, 1);
}

// round 6
// speedup vs baseline: 1.9707x; 1.9707x over previous
#include <cuda_runtime.h>
#include <cuda_bf16.h>
#include <math.h>
#include <stdint.h>

#define BB 8
#define SS 1024
#define EE 512
#define HH 8
#define DD 64

// ---------------- scratch (__device__ globals; no allocation) ---------------
__device__ __nv_bfloat16 g_xh[3L*8192*512];    // q,k,v bf16 hi (proj inputs)
__device__ __nv_bfloat16 g_xl[3L*8192*512];    // q,k,v bf16 lo
__device__ __nv_bfloat16 g_wh[3L*512*512];     // Wk,Wv,Wo hi
__device__ __nv_bfloat16 g_wl[3L*512*512];     // Wk,Wv,Wo lo
__device__ __nv_bfloat16 g_qbh[BB*HH*SS*DD];   // projected Q heads bf16 hi/lo
__device__ __nv_bfloat16 g_qbl[BB*HH*SS*DD];
__device__ __nv_bfloat16 g_kbh[BB*HH*SS*DD];   // projected K heads
__device__ __nv_bfloat16 g_kbl[BB*HH*SS*DD];
__device__ __nv_bfloat16 g_vth[BB*HH*DD*SS];   // projected V, TRANSPOSED [z][d][s]
__device__ __nv_bfloat16 g_vtl[BB*HH*DD*SS];
__device__ float         g_sc[64L*SS*SS];      // scores [z][i][j] fp32 (256MB)
__device__ __nv_bfloat16 g_ph[64L*SS*SS];      // probs bf16 hi
__device__ __nv_bfloat16 g_pl[64L*SS*SS];      // probs bf16 lo
__device__ __nv_bfloat16 g_aoh[8192L*512];     // attention out hi
__device__ __nv_bfloat16 g_aol[8192L*512];     // attention out lo

// ---------------- helpers ---------------------------------------------------
__device__ __forceinline__ uint32_t smem_u32(const void* p) {
    uint32_t a;
    asm("{ .reg .u64 t; cvta.to.shared.u64 t, %1; cvt.u32.u64 %0, t; }"
        : "=r"(a) : "l"(p));
    return a;
}
__device__ __forceinline__ void ldsm_x4(uint32_t r[4], uint32_t addr) {
    asm volatile("ldmatrix.sync.aligned.m8n8.x4.shared.b16 {%0,%1,%2,%3}, [%4];"
        : "=r"(r[0]), "=r"(r[1]), "=r"(r[2]), "=r"(r[3]) : "r"(addr));
}
__device__ __forceinline__ void ldsm_x2(uint32_t r[2], uint32_t addr) {
    asm volatile("ldmatrix.sync.aligned.m8n8.x2.shared.b16 {%0,%1}, [%2];"
        : "=r"(r[0]), "=r"(r[1]) : "r"(addr));
}
__device__ __forceinline__ void mma_bf16(float c[4], const uint32_t a[4],
                                         const uint32_t b[2]) {
    asm volatile(
        "mma.sync.aligned.m16n8k16.row.col.f32.bf16.bf16.f32 "
        "{%0,%1,%2,%3}, {%4,%5,%6,%7}, {%8,%9}, {%0,%1,%2,%3};"
        : "+f"(c[0]), "+f"(c[1]), "+f"(c[2]), "+f"(c[3])
        : "r"(a[0]), "r"(a[1]), "r"(a[2]), "r"(a[3]), "r"(b[0]), "r"(b[1]));
}
__device__ __forceinline__ float warpMax(float v) {
    #pragma unroll
    for (int o = 16; o > 0; o >>= 1) v = fmaxf(v, __shfl_xor_sync(0xffffffffu, v, o));
    return v;
}
__device__ __forceinline__ float warpSum(float v) {
    #pragma unroll
    for (int o = 16; o > 0; o >>= 1) v += __shfl_xor_sync(0xffffffffu, v, o);
    return v;
}

// ============================================================================
// Split kernel: fp32 -> bf16 (hi, lo) for q/k/v and Wk/Wv/Wo.
// ============================================================================
__global__ __launch_bounds__(256)
void split_kernel(const float* __restrict__ q, const float* __restrict__ k,
                  const float* __restrict__ v,
                  const float* __restrict__ Wk, const float* __restrict__ Wv,
                  const float* __restrict__ Wo)
{
    const long NX4 = 3L * 8192 * 512 / 4;
    const long NW4 = 3L * 512 * 512 / 4;
    long i4 = (long)blockIdx.x * blockDim.x + threadIdx.x;
    if (i4 >= NX4 + NW4) return;

    const float* src;
    __nv_bfloat16 *dh, *dl;
    long off4;
    if (i4 < NX4) {
        long z = i4 >> 20;
        off4 = i4 & ((1L << 20) - 1);
        src = (z == 0) ? q : ((z == 1) ? k : v);
        dh = g_xh + z * (8192L * 512);
        dl = g_xl + z * (8192L * 512);
    } else {
        long j4 = i4 - NX4;
        long w = j4 / 65536;
        off4 = j4 - w * 65536;
        src = (w == 0) ? Wk : ((w == 1) ? Wv : Wo);
        dh = g_wh + w * (512L * 512);
        dl = g_wl + w * (512L * 512);
    }
    float4 x = *(const float4*)(src + off4 * 4);
    __nv_bfloat16 h0 = __float2bfloat16(x.x), h1 = __float2bfloat16(x.y);
    __nv_bfloat16 h2 = __float2bfloat16(x.z), h3 = __float2bfloat16(x.w);
    __nv_bfloat162 hp0(h0, h1), hp1(h2, h3);
    __nv_bfloat162 lp0(__float2bfloat16(x.x - __bfloat162float(h0)),
                       __float2bfloat16(x.y - __bfloat162float(h1)));
    __nv_bfloat162 lp1(__float2bfloat16(x.z - __bfloat162float(h2)),
                       __float2bfloat16(x.w - __bfloat162float(h3)));
    *(__nv_bfloat162*)(dh + off4 * 4)     = hp0;
    *(__nv_bfloat162*)(dh + off4 * 4 + 2) = hp1;
    *(__nv_bfloat162*)(dl + off4 * 4)     = lp0;
    *(__nv_bfloat162*)(dl + off4 * 4 + 2) = lp1;
}

// ============================================================================
// Tensor-core GEMM (3x bf16 split): C[128,128] = A @ B^T + bias
//   mode 0 (z): A=split(q/k/v), B=split(Wk/Wk/Wv); C -> bf16 hi/lo head layout
//               (z==2: V written TRANSPOSED [z][d][s])
//   mode 1:     A=split(ao),    B=split(Wo);       C -> fp32 out
// ============================================================================
#define TPAD 144
#define TSZ  18432     // 128*144
#define GEMM_SMEM (4*TSZ)

__global__ __launch_bounds__(256, 1)
void gemm_bf16(const float* __restrict__ bk, const float* __restrict__ bv,
               const float* __restrict__ bo, float* __restrict__ out, int mode)
{
    extern __shared__ char sm[];
    const uint32_t sb = smem_u32(sm);
    const int tid = threadIdx.x;
    const int wid = tid >> 5;
    const int lane = tid & 31;

    const __nv_bfloat16 *Ah, *Al, *Bh, *Bl;
    const float* bias;
    __nv_bfloat16 *Ybh = 0, *Ybl = 0;
    int z = 0;
    if (mode == 0) {
        z = blockIdx.z;
        Ah = g_xh + z * (8192L * 512);
        Al = g_xl + z * (8192L * 512);
        long w = (z == 2) ? 1 : 0;
        Bh = g_wh + w * (512L * 512);
        Bl = g_wl + w * (512L * 512);
        bias = (z == 2) ? bv : bk;
        Ybh = (z == 0) ? g_qbh : ((z == 1) ? g_kbh : g_vth);
        Ybl = (z == 0) ? g_qbl : ((z == 1) ? g_kbl : g_vtl);
    } else {
        Ah = g_aoh; Al = g_aol;
        Bh = g_wh + 2 * (512L * 512);
        Bl = g_wl + 2 * (512L * 512);
        bias = bo;
    }

    const int m0 = blockIdx.x * 128;
    const int n0 = blockIdx.y * 128;
    const int wm = (wid >> 2) * 64;
    const int wn = (wid & 3) * 32;

    const uint32_t sA_h = sb;
    const uint32_t sA_l = sb + TSZ;
    const uint32_t sB_h = sb + 2*TSZ;
    const uint32_t sB_l = sb + 3*TSZ;

    float c[4][4][4];
    #pragma unroll
    for (int a = 0; a < 4; a++)
        #pragma unroll
        for (int b = 0; b < 4; b++)
            #pragma unroll
            for (int d = 0; d < 4; d++) c[a][b][d] = 0.f;

    for (int ch = 0; ch < 8; ch++) {
        __syncthreads();
        #pragma unroll
        for (int i = 0; i < 16; i++) {
            int slot = tid + i * 256;
            int arr  = slot >> 10;
            int r    = (slot >> 3) & 127;
            int cg   = slot & 7;
            const __nv_bfloat16* src =
                (arr == 0) ? Ah : ((arr == 1) ? Al : ((arr == 2) ? Bh : Bl));
            int grow = ((arr < 2) ? m0 : n0) + r;
            uint4 vdat = *(const uint4*)(src + (long)grow * 512 + ch * 64 + cg * 8);
            *(uint4*)(sm + arr * TSZ + r * TPAD + cg * 16) = vdat;
        }
        __syncthreads();

        #pragma unroll
        for (int ks = 0; ks < 4; ks++) {
            uint32_t bh[4][2], bl[4][2];
            #pragma unroll
            for (int ni = 0; ni < 4; ni++) {
                uint32_t addr = (uint32_t)((wn + ni*8 + (lane & 7)) * TPAD
                               + (ks*16 + ((lane >> 3) & 1) * 8) * 2);
                ldsm_x2(bh[ni], sB_h + addr);
                ldsm_x2(bl[ni], sB_l + addr);
            }
            #pragma unroll
            for (int mi = 0; mi < 4; mi++) {
                uint32_t addr = (uint32_t)((wm + mi*16 + (lane & 15)) * TPAD
                               + (ks*16 + (lane >> 4) * 8) * 2);
                uint32_t ah[4], al[4];
                ldsm_x4(ah, sA_h + addr);
                ldsm_x4(al, sA_l + addr);
                #pragma unroll
                for (int ni = 0; ni < 4; ni++) {
                    mma_bf16(c[mi][ni], ah, bh[ni]);
                    mma_bf16(c[mi][ni], ah, bl[ni]);
                    mma_bf16(c[mi][ni], al, bh[ni]);
                }
            }
        }
    }

    const int qrow = lane >> 2;
    const int qcol = (lane & 3) * 2;
    #pragma unroll
    for (int mi = 0; mi < 4; mi++) {
        #pragma unroll
        for (int ni = 0; ni < 4; ni++) {
            #pragma unroll
            for (int half = 0; half < 2; half++) {
                int m  = m0 + wm + mi*16 + qrow + half*8;
                int cn = n0 + wn + ni*8 + qcol;
                float x0 = c[mi][ni][half*2 + 0] + bias[cn];
                float x1 = c[mi][ni][half*2 + 1] + bias[cn + 1];
                __nv_bfloat16 h0 = __float2bfloat16(x0);
                __nv_bfloat16 h1 = __float2bfloat16(x1);
                __nv_bfloat16 l0 = __float2bfloat16(x0 - __bfloat162float(h0));
                __nv_bfloat16 l1 = __float2bfloat16(x1 - __bfloat162float(h1));
                if (mode == 0) {
                    int b = m >> 10, s = m & 1023;
                    int h = cn >> 6, d = cn & 63;
                    if (z == 2) {   // V: transposed [z][d][s]
                        long ti = ((long)(b*HH + h) * DD + d) * SS + s;
                        Ybh[ti] = h0;      Ybl[ti] = l0;
                        Ybh[ti + SS] = h1; Ybl[ti + SS] = l1;
                    } else {
                        long idx = (((long)(b*HH + h)) * SS + s) * DD + d;
                        *(__nv_bfloat162*)&Ybh[idx] = __nv_bfloat162(h0, h1);
                        *(__nv_bfloat162*)&Ybl[idx] = __nv_bfloat162(l0, l1);
                    }
                } else {
                    *(float2*)&out[(long)m * 512 + cn] = make_float2(x0, x1);
                }
            }
        }
    }
}

// ============================================================================
// Scores kernel: g_sc[z, i, j] = Q[i]·K[j] / 8 for tile (it, jt), jt <= it.
// 128x128 tile, K-dim = 64 (single chunk). Same mma machinery as gemm_bf16.
// ============================================================================
#define SCORES_SMEM (4*TSZ)

__global__ __launch_bounds__(256, 1)
void scores_kernel()
{
    const int jt = blockIdx.x, it = blockIdx.y, z = blockIdx.z;
    if (jt > it) return;

    extern __shared__ char sm[];
    const uint32_t sb = smem_u32(sm);
    const int tid = threadIdx.x;
    const int wid = tid >> 5;
    const int lane = tid & 31;

    const long base = (long)z * SS * DD;
    const __nv_bfloat16* Qh = g_qbh + base;
    const __nv_bfloat16* Ql = g_qbl + base;
    const __nv_bfloat16* Kh = g_kbh + base;
    const __nv_bfloat16* Kl = g_kbl + base;

    const int m0 = it * 128;
    const int n0 = jt * 128;
    const int wm = (wid >> 2) * 64;
    const int wn = (wid & 3) * 32;

    // stage 4 tiles [128][64] bf16: Qh, Ql, Kh, Kl
    #pragma unroll
    for (int i = 0; i < 16; i++) {
        int slot = tid + i * 256;
        int arr  = slot >> 10;
        int r    = (slot >> 3) & 127;
        int cg   = slot & 7;
        const __nv_bfloat16* src =
            (arr == 0) ? Qh : ((arr == 1) ? Ql : ((arr == 2) ? Kh : Kl));
        int grow = ((arr < 2) ? m0 : n0) + r;
        uint4 v4 = *(const uint4*)(src + (long)grow * DD + cg * 8);
        *(uint4*)(sm + arr * TSZ + r * TPAD + cg * 16) = v4;
    }
    __syncthreads();

    float c[4][4][4];
    #pragma unroll
    for (int a = 0; a < 4; a++)
        #pragma unroll
        for (int b = 0; b < 4; b++)
            #pragma unroll
            for (int d = 0; d < 4; d++) c[a][b][d] = 0.f;

    #pragma unroll
    for (int ks = 0; ks < 4; ks++) {
        uint32_t bh[4][2], bl[4][2];
        #pragma unroll
        for (int ni = 0; ni < 4; ni++) {
            uint32_t addr = (uint32_t)((wn + ni*8 + (lane & 7)) * TPAD
                           + (ks*16 + ((lane >> 3) & 1) * 8) * 2);
            ldsm_x2(bh[ni], sb + 2*TSZ + addr);
            ldsm_x2(bl[ni], sb + 3*TSZ + addr);
        }
        #pragma unroll
        for (int mi = 0; mi < 4; mi++) {
            uint32_t addr = (uint32_t)((wm + mi*16 + (lane & 15)) * TPAD
                           + (ks*16 + (lane >> 4) * 8) * 2);
            uint32_t ah[4], al[4];
            ldsm_x4(ah, sb + addr);
            ldsm_x4(al, sb + TSZ + addr);
            #pragma unroll
            for (int ni = 0; ni < 4; ni++) {
                mma_bf16(c[mi][ni], ah, bh[ni]);
                mma_bf16(c[mi][ni], ah, bl[ni]);
                mma_bf16(c[mi][ni], al, bh[ni]);
            }
        }
    }

    float* dst = g_sc + ((long)z << 20);
    const int qrow = lane >> 2;
    const int qcol = (lane & 3) * 2;
    #pragma unroll
    for (int mi = 0; mi < 4; mi++) {
        #pragma unroll
        for (int ni = 0; ni < 4; ni++) {
            #pragma unroll
            for (int half = 0; half < 2; half++) {
                int m  = m0 + wm + mi*16 + qrow + half*8;
                int cn = n0 + wn + ni*8 + qcol;
                float2 o;
                o.x = c[mi][ni][half*2 + 0] * 0.125f;
                o.y = c[mi][ni][half*2 + 1] * 0.125f;
                *(float2*)&dst[(long)m * SS + cn] = o;
            }
        }
    }
}

// ============================================================================
// Softmax kernel: one warp per row. softmax -> suffix-scan decay -> softmax.
// Reads g_sc fp32, writes g_ph/g_pl bf16 hi/lo (zeros up to 128-boundary).
// 8 rows/CTA, 32KB smem, no CTA-wide barriers.
// ============================================================================
__global__ __launch_bounds__(256)
void softmax_kernel(const float* __restrict__ gammas)
{
    __shared__ float rows[8][1024];
    const int tid = threadIdx.x;
    const int w = tid >> 5;
    const int lane = tid & 31;

    const long gr = (long)blockIdx.x * 8 + w;
    const int z = (int)(gr >> 10);
    const int i = (int)(gr & 1023);
    const long rbase = ((long)z << 20) + ((long)i << 10);
    __nv_bfloat16* dh = g_ph + rbase;
    __nv_bfloat16* dl = g_pl + rbase;
    const int jend = ((i >> 7) + 1) << 7;

    if (i == 0) {   // zero_pad: first query row -> zero probs
        const uint2 zz = make_uint2(0u, 0u);
        for (int j = lane * 4; j < 128; j += 128) {
            *(uint2*)(dh + j) = zz;
            *(uint2*)(dl + j) = zz;
        }
        return;
    }

    const float gamma = -log1pf(expf(gammas[z & 7]));
    float* row = rows[w];

    for (int j = lane * 4; j < jend; j += 128)
        *(float4*)&row[j] = *(const float4*)(g_sc + rbase + j);
    __syncwarp();

    // softmax #1 stats
    float mx = -3.4e38f;
    for (int j = lane; j <= i; j += 32) mx = fmaxf(mx, row[j]);
    mx = warpMax(mx);
    float sum = 0.f;
    for (int j = lane; j <= i; j += 32) sum += __expf(row[j] - mx);
    sum = warpSum(sum);
    const float inv = 1.f / sum;

    // inclusive scan of probs; suffix = 1 - prefix; decay applied to scores
    float carry = 0.f;
    const int nch = (i >> 5) + 1;
    for (int ccc = 0; ccc < nch; ccc++) {
        int j = ccc*32 + lane;
        float sorig = (j <= i) ? row[j] : 0.f;
        float e = (j <= i) ? __expf(sorig - mx) * inv : 0.f;
        float incl = e;
        #pragma unroll
        for (int o = 1; o < 32; o <<= 1) {
            float t2 = __shfl_up_sync(0xffffffffu, incl, o);
            if (lane >= o) incl += t2;
        }
        float pref = carry + incl;
        carry = __shfl_sync(0xffffffffu, pref, 31);
        float suffix = 1.f - pref;
        float pos = (float)(i - j);
        float dist = sqrtf(fmaxf(suffix * pos, 0.f));
        float eff = __expf(dist * gamma);
        eff = fminf(fmaxf(eff, 1e-5f), 1e5f);
        if (j <= i) row[j] = sorig * eff;
    }

    // softmax #2
    float m2 = -3.4e38f;
    for (int j = lane; j <= i; j += 32) m2 = fmaxf(m2, row[j]);
    m2 = warpMax(m2);
    float s2 = 0.f;
    for (int j = lane; j <= i; j += 32) s2 += __expf(row[j] - m2);
    s2 = warpSum(s2);
    const float inv2 = 1.f / s2;
    for (int j = lane; j < jend; j += 32)
        row[j] = (j <= i) ? __expf(row[j] - m2) * inv2 : 0.f;
    __syncwarp();

    // store bf16 hi/lo
    for (int j = lane * 4; j < jend; j += 128) {
        float4 p = *(const float4*)&row[j];
        __nv_bfloat16 h0 = __float2bfloat16(p.x), h1 = __float2bfloat16(p.y);
        __nv_bfloat16 h2 = __float2bfloat16(p.z), h3 = __float2bfloat16(p.w);
        __nv_bfloat162 hh0(h0, h1), hh1(h2, h3);
        __nv_bfloat162 ll0(__float2bfloat16(p.x - __bfloat162float(h0)),
                           __float2bfloat16(p.y - __bfloat162float(h1)));
        __nv_bfloat162 ll1(__float2bfloat16(p.z - __bfloat162float(h2)),
                           __float2bfloat16(p.w - __bfloat162float(h3)));
        *(__nv_bfloat162*)(dh + j)     = hh0;
        *(__nv_bfloat162*)(dh + j + 2) = hh1;
        *(__nv_bfloat162*)(dl + j)     = ll0;
        *(__nv_bfloat162*)(dl + j + 2) = ll1;
    }
}

// ============================================================================
// PV kernel: out[i, d] = sum_j P[i,j] * V[j,d] per (z). Tile: 128 i x 64 d.
// A = P hi/lo [128][64-j chunks] from gmem; B = V^T hi/lo [64 d][64 j].
// K-loop over j chunks of 64, jc < 2*(it+1) (causal; P has zeros to boundary).
// ============================================================================
#define PV_SA_H 0
#define PV_SA_L TSZ
#define PV_SB_H (2*TSZ)
#define PV_SB_L (2*TSZ + 9216)
#define PV_SMEM (2*TSZ + 2*9216)

__global__ __launch_bounds__(256, 1)
void pv_kernel()
{
    extern __shared__ char sm[];
    const uint32_t sb = smem_u32(sm);
    const int it = blockIdx.x, z = blockIdx.y;
    const int tid = threadIdx.x;
    const int wid = tid >> 5;
    const int lane = tid & 31;

    const int i0 = it * 128;
    const int wm = (wid >> 2) * 64;     // 2 warp rows x 64
    const int wn = (wid & 3) * 16;      // 4 warp cols x 16 (of 64 d)

    const __nv_bfloat16* Ph = g_ph + ((long)z << 20);
    const __nv_bfloat16* Pl = g_pl + ((long)z << 20);
    const __nv_bfloat16* Vh = g_vth + (long)z * DD * SS;
    const __nv_bfloat16* Vl = g_vtl + (long)z * DD * SS;

    float c[4][2][4];
    #pragma unroll
    for (int a = 0; a < 4; a++)
        #pragma unroll
        for (int b = 0; b < 2; b++)
            #pragma unroll
            for (int d = 0; d < 4; d++) c[a][b][d] = 0.f;

    const int njc = 2 * (it + 1);
    for (int jc = 0; jc < njc; jc++) {
        __syncthreads();
        // stage P tiles [128][64] hi/lo (1024 slots each) + V^T [64][64] (512 each)
        #pragma unroll
        for (int i = 0; i < 12; i++) {
            int slot = tid + i * 256;          // 0..3071
            uint4 v4;
            if (slot < 2048) {
                const __nv_bfloat16* src = (slot < 1024) ? Ph : Pl;
                int r  = (slot >> 3) & 127;
                int cg = slot & 7;
                v4 = *(const uint4*)(src + (long)(i0 + r) * SS + jc*64 + cg*8);
                int off = (slot < 1024) ? PV_SA_H : PV_SA_L;
                *(uint4*)(sm + off + r * TPAD + cg * 16) = v4;
            } else {
                int s2 = slot - 2048;          // 0..1023
                const __nv_bfloat16* src = (s2 < 512) ? Vh : Vl;
                int r  = (s2 >> 3) & 63;
                int cg = s2 & 7;
                v4 = *(const uint4*)(src + (long)r * SS + jc*64 + cg*8);
                int off = (s2 < 512) ? PV_SB_H : PV_SB_L;
                *(uint4*)(sm + off + r * TPAD + cg * 16) = v4;
            }
        }
        __syncthreads();

        #pragma unroll
        for (int ks = 0; ks < 4; ks++) {
            uint32_t bh[2][2], bl[2][2];
            #pragma unroll
            for (int ni = 0; ni < 2; ni++) {
                uint32_t addr = (uint32_t)((wn + ni*8 + (lane & 7)) * TPAD
                               + (ks*16 + ((lane >> 3) & 1) * 8) * 2);
                ldsm_x2(bh[ni], sb + PV_SB_H + addr);
                ldsm_x2(bl[ni], sb + PV_SB_L + addr);
            }
            #pragma unroll
            for (int mi = 0; mi < 4; mi++) {
                uint32_t addr = (uint32_t)((wm + mi*16 + (lane & 15)) * TPAD
                               + (ks*16 + (lane >> 4) * 8) * 2);
                uint32_t ah[4], al[4];
                ldsm_x4(ah, sb + PV_SA_H + addr);
                ldsm_x4(al, sb + PV_SA_L + addr);
                #pragma unroll
                for (int ni = 0; ni < 2; ni++) {
                    mma_bf16(c[mi][ni], ah, bh[ni]);
                    mma_bf16(c[mi][ni], ah, bl[ni]);
                    mma_bf16(c[mi][ni], al, bh[ni]);
                }
            }
        }
    }

    // epilogue -> g_aoh/g_aol [B*S][E], bf16 hi/lo
    const int b = z >> 3, h = z & 7;
    const int qrow = lane >> 2;
    const int qcol = (lane & 3) * 2;
    #pragma unroll
    for (int mi = 0; mi < 4; mi++) {
        #pragma unroll
        for (int ni = 0; ni < 2; ni++) {
            #pragma unroll
            for (int half = 0; half < 2; half++) {
                int s = i0 + wm + mi*16 + qrow + half*8;
                int e = h*DD + wn + ni*8 + qcol;
                long idx = ((long)(b*SS + s)) * EE + e;
                float x0 = c[mi][ni][half*2 + 0];
                float x1 = c[mi][ni][half*2 + 1];
                __nv_bfloat16 h0 = __float2bfloat16(x0);
                __nv_bfloat16 h1 = __float2bfloat16(x1);
                *(__nv_bfloat162*)&g_aoh[idx] = __nv_bfloat162(h0, h1);
                *(__nv_bfloat162*)&g_aol[idx] = __nv_bfloat162(
                    __float2bfloat16(x0 - __bfloat162float(h0)),
                    __float2bfloat16(x1 - __bfloat162float(h1)));
            }
        }
    }
}

// ============================================================================
extern "C" void kernel_launch(void* const* d_in, const int* in_sizes, int n_in,
                              void* d_out, int out_size)
{
    const float* q      = (const float*)d_in[0];
    const float* k      = (const float*)d_in[1];
    const float* v      = (const float*)d_in[2];
    const float* Wk     = (const float*)d_in[3];
    const float* bk     = (const float*)d_in[4];
    const float* Wv     = (const float*)d_in[5];
    const float* bv     = (const float*)d_in[6];
    const float* Wo     = (const float*)d_in[7];
    const float* bo     = (const float*)d_in[8];
    const float* gammas = (const float*)d_in[9];
    float* out = (float*)d_out;

    cudaFuncSetAttribute(gemm_bf16, cudaFuncAttributeMaxDynamicSharedMemorySize,
                         GEMM_SMEM);
    cudaFuncSetAttribute(scores_kernel, cudaFuncAttributeMaxDynamicSharedMemorySize,
                         SCORES_SMEM);
    cudaFuncSetAttribute(pv_kernel, cudaFuncAttributeMaxDynamicSharedMemorySize,
                         PV_SMEM);

    const long total4 = 3L*8192*512/4 + 3L*512*512/4;
    split_kernel<<<(int)((total4 + 255) / 256), 256>>>(q, k, v, Wk, Wv, Wo);
    gemm_bf16<<<dim3(64, 4, 3), 256, GEMM_SMEM>>>(bk, bv, bo, out, 0);
    scores_kernel<<<dim3(8, 8, 64), 256, SCORES_SMEM>>>();
    softmax_kernel<<<64*1024/8, 256>>>(gammas);
    pv_kernel<<<dim3(8, 64), 256, PV_SMEM>>>();
    gemm_bf16<<<dim3(64, 4, 1), 256, GEMM_SMEM>>>(bk, bv, bo, out, 1);
}